// round 9
// baseline (speedup 1.0000x reference)
#include <cuda_runtime.h>
#include <math.h>
#include <stdint.h>

// out[i] = sum_{j<512} r[batch[i][j]] + log(n_pos / n_neg)
//
// r (201KB) staged into SMEM via TWO TMA chunks with separate mbarriers:
//   chunk A = r[0 : 25136)        (100544 B)
//   chunk B = r[25136 : 50256)    (100480 B)  (+4B scalar tail)
// Warps preload all six index rows into registers, then overlap the
// second half of staging with predicated lower-half gathers (pass 1),
// finishing upper-half gathers (pass 2) once chunk B lands.
// 148 CTAs x 512 threads (16 warps).

#define ROWS   16384
#define LEN    512
#define VOCAB  50257
#define NBLK   148
#define NTHR   512
#define NWARP  (NTHR / 32)           // 16
#define GWARPS (NBLK * NWARP)        // 2368;  ROWS = 6*GWARPS + 2176

#define HSPLIT     25136                     // lower-chunk element count
#define A_BYTES    (HSPLIT * 4)              // 100544 (16B multiple)
#define RS_BULK    ((VOCAB * 4 / 16) * 16)   // 201024
#define B_BYTES    (RS_BULK - A_BYTES)       // 100480 (16B multiple)
#define MBAR_OFF   201040
#define SMEM_TOTAL (MBAR_OFF + 32)

__device__ __forceinline__ uint32_t smem_u32(const void* p) {
    uint32_t a;
    asm("{ .reg .u64 t; cvta.to.shared.u64 t, %1; cvt.u32.u64 %0, t; }"
        : "=r"(a) : "l"(p));
    return a;
}

__device__ __forceinline__ void bar_wait(uint32_t bar, uint32_t parity) {
    uint32_t done;
    asm volatile(
        "{ .reg .pred p;\n"
        "  mbarrier.try_wait.parity.acquire.cta.shared::cta.b64 p, [%1], %2;\n"
        "  selp.b32 %0, 1, 0, p; }"
        : "=r"(done) : "r"(bar), "r"(parity) : "memory");
    if (!done) {
        asm volatile(
            "{ .reg .pred P1;\n"
            "W_LOOP:\n"
            "  mbarrier.try_wait.parity.acquire.cta.shared::cta.b64 P1, [%0], %1, 0x989680;\n"
            "  @P1 bra.uni W_DONE;\n"
            "  bra.uni W_LOOP;\n"
            "W_DONE: }"
            :: "r"(bar), "r"(parity) : "memory");
    }
}

__device__ __forceinline__ void load_row(const int* __restrict__ batch,
                                         int row, int lane, int4* v)
{
    const int4* __restrict__ bp =
        reinterpret_cast<const int4*>(batch + (size_t)row * LEN);
#pragma unroll
    for (int i = 0; i < 4; i++)
        v[i] = bp[lane + 32 * i];
}

__device__ __forceinline__ void pass_lower(const float* __restrict__ rs,
                                           const int4* v, float& acc)
{
#pragma unroll
    for (int i = 0; i < 4; i++) {
        if (v[i].x < HSPLIT) acc += rs[v[i].x];
        if (v[i].y < HSPLIT) acc += rs[v[i].y];
        if (v[i].z < HSPLIT) acc += rs[v[i].z];
        if (v[i].w < HSPLIT) acc += rs[v[i].w];
    }
}

__device__ __forceinline__ void pass_upper(const float* __restrict__ rs,
                                           const int4* v, float& acc)
{
#pragma unroll
    for (int i = 0; i < 4; i++) {
        if (v[i].x >= HSPLIT) acc += rs[v[i].x];
        if (v[i].y >= HSPLIT) acc += rs[v[i].y];
        if (v[i].z >= HSPLIT) acc += rs[v[i].z];
        if (v[i].w >= HSPLIT) acc += rs[v[i].w];
    }
}

// Finish a pair: upper-half gathers, dual shuffle reduction, store.
__device__ __forceinline__ void finish_pair(const float* __restrict__ rs,
                                            const int4* x, const int4* y,
                                            float s0, float s1,
                                            int lane, float lp,
                                            float* __restrict__ out,
                                            int row0, int row1)
{
    pass_upper(rs, x, s0);
    pass_upper(rs, y, s1);
#pragma unroll
    for (int o = 16; o > 0; o >>= 1) {
        s0 += __shfl_xor_sync(0xFFFFFFFFu, s0, o);
        s1 += __shfl_xor_sync(0xFFFFFFFFu, s1, o);
    }
    if (lane == 0) {
        out[row0] = s0 + lp;
        out[row1] = s1 + lp;
    }
}

__global__ __launch_bounds__(NTHR, 1) void nb_split_kernel(
    const int* __restrict__ batch,
    const float* __restrict__ r,
    const int* __restrict__ n_pos,
    const int* __restrict__ n_neg,
    float* __restrict__ out)
{
    extern __shared__ float rs[];
    const int tid  = threadIdx.x;
    const int warp = tid >> 5;
    const int lane = tid & 31;
    const int gw   = blockIdx.x * NWARP + warp;

    char* sm = reinterpret_cast<char*>(rs);
    const uint32_t rs_s  = smem_u32(sm);
    const uint32_t mbarA = smem_u32(sm + MBAR_OFF);
    const uint32_t mbarB = smem_u32(sm + MBAR_OFF + 8);

    if (tid == 0) {
        rs[VOCAB - 1] = r[VOCAB - 1];           // 4B tail TMA can't cover
        asm volatile("mbarrier.init.shared.b64 [%0], %1;" :: "r"(mbarA), "r"(1) : "memory");
        asm volatile("mbarrier.init.shared.b64 [%0], %1;" :: "r"(mbarB), "r"(1) : "memory");
    }
    __syncthreads();

    // ---- TMA staging FIRST (critical path), two chunks / two barriers ----
    if (tid == 0) {
        asm volatile("mbarrier.arrive.expect_tx.shared.b64 _, [%0], %1;"
                     :: "r"(mbarA), "r"((uint32_t)A_BYTES) : "memory");
        asm volatile(
            "cp.async.bulk.shared::cta.global.mbarrier::complete_tx::bytes "
            "[%0], [%1], %2, [%3];"
            :: "r"(rs_s), "l"((const char*)r), "r"((uint32_t)A_BYTES), "r"(mbarA)
            : "memory");
        asm volatile("mbarrier.arrive.expect_tx.shared.b64 _, [%0], %1;"
                     :: "r"(mbarB), "r"((uint32_t)B_BYTES) : "memory");
        asm volatile(
            "cp.async.bulk.shared::cta.global.mbarrier::complete_tx::bytes "
            "[%0], [%1], %2, [%3];"
            :: "r"(rs_s + (uint32_t)A_BYTES),
               "l"((const char*)r + A_BYTES),
               "r"((uint32_t)B_BYTES), "r"(mbarB)
            : "memory");
    }

    // ---- Pre-issue ALL six rows' index loads (24 LDG.128 per warp) ----
    int4 A[4], B[4], C[4], D[4], E[4], F[4];
    load_row(batch, gw + 0 * GWARPS, lane, A);
    load_row(batch, gw + 1 * GWARPS, lane, B);
    load_row(batch, gw + 2 * GWARPS, lane, C);
    load_row(batch, gw + 3 * GWARPS, lane, D);
    load_row(batch, gw + 4 * GWARPS, lane, E);
    load_row(batch, gw + 5 * GWARPS, lane, F);
    const bool has7 = (gw + 6 * GWARPS) < ROWS;   // gw < 2176

    const float lp = logf((float)__ldg(n_pos) / (float)__ldg(n_neg));

    // ---- Pass 1: lower-half gathers as soon as chunk A lands ----
    bar_wait(mbarA, 0);
    float sA = 0.f, sB = 0.f, sC = 0.f, sD = 0.f, sE = 0.f, sF = 0.f;
    pass_lower(rs, A, sA);
    pass_lower(rs, B, sB);
    pass_lower(rs, C, sC);
    pass_lower(rs, D, sD);
    pass_lower(rs, E, sE);
    pass_lower(rs, F, sF);

    // ---- Pass 2: upper half once chunk B lands ----
    bar_wait(mbarB, 0);

    finish_pair(rs, A, B, sA, sB, lane, lp, out, gw + 0 * GWARPS, gw + 1 * GWARPS);

    // Row G reuses A/B's dead registers; issued well before its use.
    int4 G[4];
    if (has7) load_row(batch, gw + 6 * GWARPS, lane, G);

    finish_pair(rs, C, D, sC, sD, lane, lp, out, gw + 2 * GWARPS, gw + 3 * GWARPS);
    finish_pair(rs, E, F, sE, sF, lane, lp, out, gw + 4 * GWARPS, gw + 5 * GWARPS);

    if (has7) {
        float a = 0.f, b = 0.f;
#pragma unroll
        for (int i = 0; i < 4; i++) {
            a += rs[G[i].x];  b += rs[G[i].y];
            a += rs[G[i].z];  b += rs[G[i].w];
        }
        float s = a + b;
#pragma unroll
        for (int o = 16; o > 0; o >>= 1)
            s += __shfl_xor_sync(0xFFFFFFFFu, s, o);
        if (lane == 0)
            out[gw + 6 * GWARPS] = s + lp;
    }
}

extern "C" void kernel_launch(void* const* d_in, const int* in_sizes, int n_in,
                              void* d_out, int out_size)
{
    const int*   batch = (const int*)  d_in[0];
    const float* r     = (const float*)d_in[1];
    const int*   npos  = (const int*)  d_in[2];
    const int*   nneg  = (const int*)  d_in[3];
    float*       out   = (float*)      d_out;

    static int configured = 0;
    if (!configured) {
        cudaFuncSetAttribute(nb_split_kernel,
                             cudaFuncAttributeMaxDynamicSharedMemorySize,
                             SMEM_TOTAL);
        configured = 1;
    }

    nb_split_kernel<<<NBLK, NTHR, SMEM_TOTAL>>>(batch, r, npos, nneg, out);
}

// round 10
// speedup vs baseline: 1.1376x; 1.1376x over previous
#include <cuda_runtime.h>
#include <math.h>
#include <stdint.h>

// out[i] = sum_{j<512} r[batch[i][j]] + log(n_pos / n_neg)
//
// Dual-path index streaming (the LDG/MSHR path saturates at ~2.6TB/s):
//  - r (201KB) staged to SMEM via TMA (4 chunks, 1 barrier).
//  - 32 rows/CTA preloaded via LDG into registers (2 per warp).
//  - remaining 78/79 rows/CTA streamed via cp.async.bulk into a 14-slot
//    ring of 2KB row buffers (bypasses MSHRs). Producer = warp 15
//    lanes 0..13 (one slot each); consumers = warps 0..13 (row per warp).
// 148 CTAs x 512 threads. CTA b owns rows [start_b, start_b+cnt_b).

#define ROWS   16384
#define LEN    512
#define VOCAB  50257
#define NBLK   148
#define NTHR   512
#define NSLOT  14
#define ROW_BYTES 2048
#define LDG_ROWS  32

#define RS_BULK   ((VOCAB * 4 / 16) * 16)    // 201024
#define RBAR_OFF  201032
#define FULL_OFF(s)  (201040 + (s) * 8)
#define EMPTY_OFF(s) (201152 + (s) * 8)
#define SLOT_OFF(s)  (201280 + (s) * ROW_BYTES)
#define SMEM_TOTAL   (201280 + NSLOT * ROW_BYTES)   // 229952 <= 232448

__device__ __forceinline__ uint32_t smem_u32(const void* p) {
    uint32_t a;
    asm("{ .reg .u64 t; cvta.to.shared.u64 t, %1; cvt.u32.u64 %0, t; }"
        : "=r"(a) : "l"(p));
    return a;
}
__device__ __forceinline__ void bar_init(uint32_t bar, uint32_t cnt) {
    asm volatile("mbarrier.init.shared.b64 [%0], %1;" :: "r"(bar), "r"(cnt) : "memory");
}
__device__ __forceinline__ void bar_arrive(uint32_t bar) {
    asm volatile("mbarrier.arrive.release.cta.shared::cta.b64 _, [%0];" :: "r"(bar) : "memory");
}
__device__ __forceinline__ void bar_expect_tx(uint32_t bar, uint32_t bytes) {
    asm volatile("mbarrier.arrive.expect_tx.shared.b64 _, [%0], %1;"
                 :: "r"(bar), "r"(bytes) : "memory");
}
__device__ __forceinline__ void bar_wait(uint32_t bar, uint32_t parity) {
    uint32_t done;
    asm volatile(
        "{ .reg .pred p;\n"
        "  mbarrier.try_wait.parity.acquire.cta.shared::cta.b64 p, [%1], %2;\n"
        "  selp.b32 %0, 1, 0, p; }"
        : "=r"(done) : "r"(bar), "r"(parity) : "memory");
    while (!done) {
        asm volatile(
            "{ .reg .pred p;\n"
            "  mbarrier.try_wait.parity.acquire.cta.shared::cta.b64 p, [%1], %2, 0x989680;\n"
            "  selp.b32 %0, 1, 0, p; }"
            : "=r"(done) : "r"(bar), "r"(parity) : "memory");
    }
}
__device__ __forceinline__ void bulk_g2s(uint32_t dst, const void* src,
                                         uint32_t bytes, uint32_t bar) {
    asm volatile(
        "cp.async.bulk.shared::cta.global.mbarrier::complete_tx::bytes "
        "[%0], [%1], %2, [%3];"
        :: "r"(dst), "l"(src), "r"(bytes), "r"(bar) : "memory");
}
__device__ __forceinline__ void load_row(const int* __restrict__ batch,
                                         int row, int lane, int4* v)
{
    const int4* __restrict__ bp =
        reinterpret_cast<const int4*>(batch + (size_t)row * LEN);
#pragma unroll
    for (int i = 0; i < 4; i++)
        v[i] = bp[lane + 32 * i];
}

__global__ __launch_bounds__(NTHR, 1) void nb_dual_kernel(
    const int* __restrict__ batch,
    const float* __restrict__ r,
    const int* __restrict__ n_pos,
    const int* __restrict__ n_neg,
    float* __restrict__ out)
{
    extern __shared__ float rs[];
    char* sm = reinterpret_cast<char*>(rs);

    const int tid  = threadIdx.x;
    const int warp = tid >> 5;
    const int lane = tid & 31;
    const int b    = blockIdx.x;

    const int cnt   = 110 + (b < 104);
    const int start = b * 110 + (b < 104 ? b : 104);
    const int T     = cnt - LDG_ROWS;            // 78 or 79 TMA rows

    const uint32_t rs_s = smem_u32(sm);
    const uint32_t rbar = smem_u32(sm + RBAR_OFF);

    if (tid == 0) {
        rs[VOCAB - 1] = r[VOCAB - 1];            // 4B tail TMA can't cover
        bar_init(rbar, 1);
#pragma unroll
        for (int s = 0; s < NSLOT; s++) {
            bar_init(smem_u32(sm + FULL_OFF(s)), 1);
            bar_init(smem_u32(sm + EMPTY_OFF(s)), 1);
        }
    }
    __syncthreads();

    // ---- Stage r via TMA (warp 14, lane 0 — dedicated, no divergence) ----
    if (warp == 14 && lane == 0) {
        bar_expect_tx(rbar, (uint32_t)RS_BULK);
        const uint32_t chunk = RS_BULK / 4;
#pragma unroll
        for (int i = 0; i < 4; i++)
            bulk_g2s(rs_s + i * chunk, (const char*)r + i * chunk, chunk, rbar);
    }

    // ---- Every warp pre-issues its 2 LDG rows (overlaps everything) ----
    const int lrow0 = start + T + 2 * warp;      // 2 rows per warp, 32 total
    int4 X[4], Y[4];
    load_row(batch, lrow0 + 0, lane, X);
    load_row(batch, lrow0 + 1, lane, Y);

    const float lp = logf((float)__ldg(n_pos) / (float)__ldg(n_neg));

    // ---- Producer: warp 15, lanes 0..13 each own one ring slot ----
    if (warp == 15) {
        if (lane < NSLOT) {
            const uint32_t fb = smem_u32(sm + FULL_OFF(lane));
            const uint32_t eb = smem_u32(sm + EMPTY_OFF(lane));
            const uint32_t dst = smem_u32(sm + SLOT_OFF(lane));
            for (int k = 0; lane + NSLOT * k < T; k++) {
                if (k > 0) bar_wait(eb, (k - 1) & 1);
                bar_expect_tx(fb, ROW_BYTES);
                bulk_g2s(dst,
                         (const char*)batch +
                             (size_t)(start + lane + NSLOT * k) * ROW_BYTES,
                         ROW_BYTES, fb);
            }
        }
        __syncwarp();
    } else if (warp < 14) {
        // ---- Consumers: warp w consumes slot w, rows w + 14k ----
        const uint32_t fb = smem_u32(sm + FULL_OFF(warp));
        const uint32_t eb = smem_u32(sm + EMPTY_OFF(warp));
        const int4* __restrict__ bp =
            reinterpret_cast<const int4*>(sm + SLOT_OFF(warp));

        bar_wait(rbar, 0);                       // r resident before gathers

        for (int k = 0; warp + NSLOT * k < T; k++) {
            bar_wait(fb, k & 1);

            float a = 0.f, c = 0.f;
#pragma unroll
            for (int i = 0; i < 4; i++) {
                int4 v = bp[lane + 32 * i];
                a += rs[v.x];  c += rs[v.y];
                a += rs[v.z];  c += rs[v.w];
            }
            float s = a + c;
            __syncwarp();
            if (lane == 0) bar_arrive(eb);       // free slot ASAP

#pragma unroll
            for (int o = 16; o > 0; o >>= 1)
                s += __shfl_xor_sync(0xFFFFFFFFu, s, o);
            if (lane == 0)
                out[start + warp + NSLOT * k] = s + lp;
        }
    }

    // ---- All warps: finish their 2 LDG rows (pair-reduced) ----
    if (warp >= 14) bar_wait(rbar, 0);           // consumers already waited

    float a0 = 0.f, b0 = 0.f, a1 = 0.f, b1 = 0.f;
#pragma unroll
    for (int i = 0; i < 4; i++) {
        a0 += rs[X[i].x];  b0 += rs[X[i].y];
        a0 += rs[X[i].z];  b0 += rs[X[i].w];
        a1 += rs[Y[i].x];  b1 += rs[Y[i].y];
        a1 += rs[Y[i].z];  b1 += rs[Y[i].w];
    }
    float s0 = a0 + b0;
    float s1 = a1 + b1;
#pragma unroll
    for (int o = 16; o > 0; o >>= 1) {
        s0 += __shfl_xor_sync(0xFFFFFFFFu, s0, o);
        s1 += __shfl_xor_sync(0xFFFFFFFFu, s1, o);
    }
    if (lane == 0) {
        out[lrow0 + 0] = s0 + lp;
        out[lrow0 + 1] = s1 + lp;
    }
}

extern "C" void kernel_launch(void* const* d_in, const int* in_sizes, int n_in,
                              void* d_out, int out_size)
{
    const int*   batch = (const int*)  d_in[0];
    const float* r     = (const float*)d_in[1];
    const int*   npos  = (const int*)  d_in[2];
    const int*   nneg  = (const int*)  d_in[3];
    float*       out   = (float*)      d_out;

    static int configured = 0;
    if (!configured) {
        cudaFuncSetAttribute(nb_dual_kernel,
                             cudaFuncAttributeMaxDynamicSharedMemorySize,
                             SMEM_TOTAL);
        configured = 1;
    }

    nb_dual_kernel<<<NBLK, NTHR, SMEM_TOTAL>>>(batch, r, npos, nneg, out);
}

// round 11
// speedup vs baseline: 1.3780x; 1.2113x over previous
#include <cuda_runtime.h>
#include <math.h>
#include <stdint.h>

// out[i] = sum_{j<512} r[batch[i][j]] + log(n_pos / n_neg)
//
// R6 structure + __ldcg on the index stream. Normal cached LDGs cap at
// ~2.6TB/s (per-SM L1/MSHR line tracking); .cg bypasses L1 and reaches the
// LTS cap (~6300 B/cyc, measured equal to TMA). r (201KB) staged into SMEM
// via TMA while each warp pre-issues all six of its index rows.
// 148 CTAs x 512 threads.

#define ROWS   16384
#define LEN    512
#define VOCAB  50257
#define NBLK   148
#define NTHR   512
#define NWARP  (NTHR / 32)           // 16
#define GWARPS (NBLK * NWARP)        // 2368;  ROWS = 6*GWARPS + 2176

#define RS_BYTES   (VOCAB * 4)               // 201028
#define RS_BULK    ((RS_BYTES / 16) * 16)    // 201024
#define MBAR_OFF   201040
#define SMEM_TOTAL (MBAR_OFF + 16)

__device__ __forceinline__ uint32_t smem_u32(const void* p) {
    uint32_t a;
    asm("{ .reg .u64 t; cvta.to.shared.u64 t, %1; cvt.u32.u64 %0, t; }"
        : "=r"(a) : "l"(p));
    return a;
}

__device__ __forceinline__ void load_row(const int* __restrict__ batch,
                                         int row, int lane, int4* v)
{
    const int4* __restrict__ bp =
        reinterpret_cast<const int4*>(batch + (size_t)row * LEN);
#pragma unroll
    for (int i = 0; i < 4; i++)
        v[i] = __ldcg(bp + lane + 32 * i);   // L2-only: bypass L1/MSHR cap
}

__device__ __forceinline__ void compute_pair(const float* __restrict__ rs,
                                             const int4* x, const int4* y,
                                             int lane, float lp,
                                             float* __restrict__ out,
                                             int row0, int row1)
{
    float a0 = 0.f, b0 = 0.f, a1 = 0.f, b1 = 0.f;
#pragma unroll
    for (int i = 0; i < 4; i++) {
        a0 += rs[x[i].x];  b0 += rs[x[i].y];
        a0 += rs[x[i].z];  b0 += rs[x[i].w];
        a1 += rs[y[i].x];  b1 += rs[y[i].y];
        a1 += rs[y[i].z];  b1 += rs[y[i].w];
    }
    float s0 = a0 + b0;
    float s1 = a1 + b1;
#pragma unroll
    for (int o = 16; o > 0; o >>= 1) {
        s0 += __shfl_xor_sync(0xFFFFFFFFu, s0, o);
        s1 += __shfl_xor_sync(0xFFFFFFFFu, s1, o);
    }
    if (lane == 0) {
        out[row0] = s0 + lp;
        out[row1] = s1 + lp;
    }
}

__global__ __launch_bounds__(NTHR, 1) void nb_cg_kernel(
    const int* __restrict__ batch,
    const float* __restrict__ r,
    const int* __restrict__ n_pos,
    const int* __restrict__ n_neg,
    float* __restrict__ out)
{
    extern __shared__ float rs[];
    const int tid  = threadIdx.x;
    const int warp = tid >> 5;
    const int lane = tid & 31;
    const int gw   = blockIdx.x * NWARP + warp;

    char* smem_raw = reinterpret_cast<char*>(rs);
    const uint32_t mbar = smem_u32(smem_raw + MBAR_OFF);
    const uint32_t rs_s = smem_u32(smem_raw);

    if (tid == 0) {
        rs[VOCAB - 1] = r[VOCAB - 1];
        asm volatile("mbarrier.init.shared.b64 [%0], %1;" :: "r"(mbar), "r"(1) : "memory");
    }
    __syncthreads();

    // ---- TMA bulk staging of r into SMEM (issue FIRST — critical path) ----
    if (tid == 0) {
        asm volatile("mbarrier.arrive.expect_tx.shared.b64 _, [%0], %1;"
                     :: "r"(mbar), "r"((uint32_t)RS_BULK) : "memory");
        const uint32_t chunk = RS_BULK / 4;
#pragma unroll
        for (int i = 0; i < 4; i++) {
            asm volatile(
                "cp.async.bulk.shared::cta.global.mbarrier::complete_tx::bytes "
                "[%0], [%1], %2, [%3];"
                :: "r"(rs_s + i * chunk),
                   "l"((const char*)r + i * chunk),
                   "r"(chunk), "r"(mbar)
                : "memory");
        }
    }

    // ---- Pre-issue ALL six rows' index loads (24 LDG.E.128.CG per warp) ----
    int4 A[4], B[4], C[4], D[4], E[4], F[4];
    load_row(batch, gw + 0 * GWARPS, lane, A);
    load_row(batch, gw + 1 * GWARPS, lane, B);
    load_row(batch, gw + 2 * GWARPS, lane, C);
    load_row(batch, gw + 3 * GWARPS, lane, D);
    load_row(batch, gw + 4 * GWARPS, lane, E);
    load_row(batch, gw + 5 * GWARPS, lane, F);
    const bool has7 = (gw + 6 * GWARPS) < ROWS;   // gw < 2176

    const float lp = logf((float)__ldg(n_pos) / (float)__ldg(n_neg));

    // ---- Wait for r (acquire) ----
    {
        uint32_t done;
        asm volatile(
            "{ .reg .pred p;\n"
            "  mbarrier.try_wait.parity.acquire.cta.shared::cta.b64 p, [%1], %2;\n"
            "  selp.b32 %0, 1, 0, p; }"
            : "=r"(done) : "r"(mbar), "r"(0u) : "memory");
        if (!done) {
            asm volatile(
                "{ .reg .pred P1;\n"
                "WAIT_LOOP:\n"
                "  mbarrier.try_wait.parity.acquire.cta.shared::cta.b64 P1, [%0], %1, 0x989680;\n"
                "  @P1 bra.uni WAIT_DONE;\n"
                "  bra.uni WAIT_LOOP;\n"
                "WAIT_DONE: }"
                :: "r"(mbar), "r"(0u) : "memory");
        }
    }

    // ---- Compute: three pairs + optional 7th row ----
    compute_pair(rs, A, B, lane, lp, out, gw + 0 * GWARPS, gw + 1 * GWARPS);

    int4 G[4];
    if (has7) load_row(batch, gw + 6 * GWARPS, lane, G);

    compute_pair(rs, C, D, lane, lp, out, gw + 2 * GWARPS, gw + 3 * GWARPS);
    compute_pair(rs, E, F, lane, lp, out, gw + 4 * GWARPS, gw + 5 * GWARPS);

    if (has7) {
        float a = 0.f, b = 0.f;
#pragma unroll
        for (int i = 0; i < 4; i++) {
            a += rs[G[i].x];  b += rs[G[i].y];
            a += rs[G[i].z];  b += rs[G[i].w];
        }
        float s = a + b;
#pragma unroll
        for (int o = 16; o > 0; o >>= 1)
            s += __shfl_xor_sync(0xFFFFFFFFu, s, o);
        if (lane == 0)
            out[gw + 6 * GWARPS] = s + lp;
    }
}

extern "C" void kernel_launch(void* const* d_in, const int* in_sizes, int n_in,
                              void* d_out, int out_size)
{
    const int*   batch = (const int*)  d_in[0];
    const float* r     = (const float*)d_in[1];
    const int*   npos  = (const int*)  d_in[2];
    const int*   nneg  = (const int*)  d_in[3];
    float*       out   = (float*)      d_out;

    static int configured = 0;
    if (!configured) {
        cudaFuncSetAttribute(nb_cg_kernel,
                             cudaFuncAttributeMaxDynamicSharedMemorySize,
                             SMEM_TOTAL);
        configured = 1;
    }

    nb_cg_kernel<<<NBLK, NTHR, SMEM_TOTAL>>>(batch, r, npos, nneg, out);
}